// round 2
// baseline (speedup 1.0000x reference)
#include <cuda_runtime.h>

#define NP 60000
#define NM 30000
#define NN 90000
#define ETR 2000000
#define EDC 400000
#define NBINS (2*NN)

// ---------------- device scratch (static: no allocation allowed) -------------
__device__ float g_bufA[NN * 32];
__device__ float g_bufB[NN * 32];
__device__ float g_agg[NN * 2 * 32];
__device__ int   g_cnt[NBINS];
__device__ int   g_off[NBINS];
__device__ int   g_cur[NBINS];
__device__ int   g_esrc[ETR];
__device__ float g_W0[32 * 32];
__device__ float g_W1[32 * 32];

// ---------------- CSR build --------------------------------------------------
__global__ void k_zero_cnt() {
    int i = blockIdx.x * blockDim.x + threadIdx.x;
    if (i < NBINS) g_cnt[i] = 0;
}

__global__ void k_hist(const int* __restrict__ ei, const int* __restrict__ et) {
    int e = blockIdx.x * blockDim.x + threadIdx.x;
    if (e < ETR) {
        int key = ei[ETR + e] * 2 + et[e];
        atomicAdd(&g_cnt[key], 1);
    }
}

// single-block exclusive scan over 180000 bins
__global__ void k_scan() {
    __shared__ int ssum[1024];
    const int t = threadIdx.x;
    const int chunk = (NBINS + 1023) / 1024;  // 176
    int b0 = t * chunk;
    int b1 = min(b0 + chunk, NBINS);
    int s = 0;
    for (int i = b0; i < b1; i++) s += g_cnt[i];
    ssum[t] = s;
    __syncthreads();
    for (int off = 1; off < 1024; off <<= 1) {
        int tmp = (t >= off) ? ssum[t - off] : 0;
        __syncthreads();
        ssum[t] += tmp;
        __syncthreads();
    }
    int run = ssum[t] - s;  // exclusive prefix
    for (int i = b0; i < b1; i++) {
        g_off[i] = run;
        g_cur[i] = run;
        run += g_cnt[i];
    }
}

__global__ void k_scatter(const int* __restrict__ ei, const int* __restrict__ et) {
    int e = blockIdx.x * blockDim.x + threadIdx.x;
    if (e < ETR) {
        int key = ei[ETR + e] * 2 + et[e];
        int pos = atomicAdd(&g_cur[key], 1);
        g_esrc[pos] = ei[e];
    }
}

// ---------------- input transform: x0 = concat(xp@Wp+bp, xm@Wm+bm), D0=16 ----
__global__ void k_transform(const float* __restrict__ xp, const float* __restrict__ xm,
                            const float* __restrict__ Wp, const float* __restrict__ bp,
                            const float* __restrict__ Wm, const float* __restrict__ bm) {
    int idx = blockIdx.x * blockDim.x + threadIdx.x;
    int n = idx >> 4;
    int o = idx & 15;
    if (n >= NN) return;
    const float* x;
    const float* W;
    float bv;
    if (n < NP) { x = xp + (long)n * 128; W = Wp; bv = bp[o]; }
    else        { x = xm + (long)(n - NP) * 128; W = Wm; bv = bm[o]; }
    float s = bv;
#pragma unroll 8
    for (int k = 0; k < 128; k++) s += x[k] * W[k * 16 + o];
    g_bufA[n * 16 + o] = s;
}

// ---------------- per-layer: combine bases -> W_r ---------------------------
__global__ void k_precompW(const float* __restrict__ bases, const float* __restrict__ comp,
                           int ins, int outs) {
    int tid = blockIdx.x * blockDim.x + threadIdx.x;
    int sz = ins * outs;
    if (tid >= 2 * sz) return;
    int r = tid / sz;
    int io = tid - r * sz;
    float s = 0.f;
#pragma unroll
    for (int b = 0; b < 4; b++) s += comp[r * 4 + b] * bases[b * sz + io];
    if (r == 0) g_W0[io] = s;
    else        g_W1[io] = s;
}

// ---------------- segmented gather-mean: warp per (dst,rel) bin --------------
__global__ void k_aggregate(int inA, int ins) {
    int gt = blockIdx.x * blockDim.x + threadIdx.x;
    int w = gt >> 5;
    int lane = gt & 31;
    if (w >= NBINS) return;
    const float* __restrict__ xin = inA ? g_bufA : g_bufB;
    int start = g_off[w];
    int cnt = g_cnt[w];
    if (lane < ins) {
        float s0 = 0.f, s1 = 0.f;
        int i = 0;
        for (; i + 1 < cnt; i += 2) {
            int a = __ldg(&g_esrc[start + i]);
            int b = __ldg(&g_esrc[start + i + 1]);
            s0 += __ldg(&xin[a * ins + lane]);
            s1 += __ldg(&xin[b * ins + lane]);
        }
        if (i < cnt) s0 += __ldg(&xin[__ldg(&g_esrc[start + i]) * ins + lane]);
        float inv = cnt > 0 ? 1.0f / (float)cnt : 0.0f;
        g_agg[w * ins + lane] = (s0 + s1) * inv;
    }
}

// ---------------- dense combine: out = x@root + agg0@W0 + agg1@W1 + b --------
__global__ void k_combine(int inA, int ins, int outs,
                          const float* __restrict__ root, const float* __restrict__ bias,
                          int do_relu) {
    int idx = blockIdx.x * blockDim.x + threadIdx.x;
    int n = idx / outs;
    int o = idx - n * outs;
    if (n >= NN) return;
    const float* __restrict__ xin = inA ? g_bufA : g_bufB;
    float* __restrict__ xout = inA ? g_bufB : g_bufA;
    const float* xr = xin + n * ins;
    const float* a0 = g_agg + (n * 2) * ins;
    const float* a1 = a0 + ins;
    float s = bias[o];
    for (int i = 0; i < ins; i++) {
        s += xr[i] * root[i * outs + o];
        s += a0[i] * g_W0[i * outs + o];
        s += a1[i] * g_W1[i * outs + o];
    }
    if (do_relu) s = fmaxf(s, 0.f);
    xout[n * outs + o] = s;
}

// ---------------- decoder: half-warp per edge, D=16 --------------------------
__global__ void k_decode(const int* __restrict__ ei, const int* __restrict__ et,
                         const float* __restrict__ Wd0, const float* __restrict__ bd0,
                         const float* __restrict__ Wd1, const float* __restrict__ bd1,
                         float* __restrict__ out) {
    __shared__ float sW0[256], sW1[256], sb0[16], sb1[16];
    int tid = threadIdx.x;
    if (tid < 256) { sW0[tid] = Wd0[tid]; sW1[tid] = Wd1[tid]; }
    if (tid < 16) { sb0[tid] = bd0[tid]; sb1[tid] = bd1[tid]; }
    __syncthreads();
    int g = blockIdx.x * blockDim.x + tid;
    int e = g >> 4;
    int c = g & 15;
    if (e >= EDC) return;
    const float* z = g_bufA;  // final embeddings, stride 16
    int src = ei[e];
    int dst = ei[EDC + e];
    int t = et[e];
    float zs = z[src * 16 + c];
    float zd = z[dst * 16 + c];
    const float* W = (t == 0) ? sW0 : sW1;
    float h = (t == 0) ? sb0[c] : sb1[c];
#pragma unroll
    for (int i = 0; i < 16; i++) {
        float zi = __shfl_sync(0xffffffffu, zs, i, 16);
        h += zi * W[i * 16 + c];
    }
    float p = h * zd;
#pragma unroll
    for (int off = 8; off >= 1; off >>= 1)
        p += __shfl_down_sync(0xffffffffu, p, off, 16);
    if (c == 0) out[e] = p;
}

// ---------------- launch -----------------------------------------------------
extern "C" void kernel_launch(void* const* d_in, const int* in_sizes, int n_in,
                              void* d_out, int out_size) {
    const float* xp   = (const float*)d_in[0];
    const float* xm   = (const float*)d_in[1];
    const int*   tei  = (const int*)d_in[2];
    const int*   tet  = (const int*)d_in[3];
    const int*   pei  = (const int*)d_in[4];
    const int*   pet  = (const int*)d_in[5];
    const int*   nei  = (const int*)d_in[6];
    const int*   net_ = (const int*)d_in[7];
    const float* Wp   = (const float*)d_in[8];
    const float* bp   = (const float*)d_in[9];
    const float* Wm   = (const float*)d_in[10];
    const float* bm   = (const float*)d_in[11];
    const float* Wd0  = (const float*)d_in[12];
    const float* bd0  = (const float*)d_in[13];
    const float* Wd1  = (const float*)d_in[14];
    const float* bd1  = (const float*)d_in[15];
    const float* bases[4] = {(const float*)d_in[16], (const float*)d_in[20],
                             (const float*)d_in[24], (const float*)d_in[28]};
    const float* comp[4]  = {(const float*)d_in[17], (const float*)d_in[21],
                             (const float*)d_in[25], (const float*)d_in[29]};
    const float* root[4]  = {(const float*)d_in[18], (const float*)d_in[22],
                             (const float*)d_in[26], (const float*)d_in[30]};
    const float* bias[4]  = {(const float*)d_in[19], (const float*)d_in[23],
                             (const float*)d_in[27], (const float*)d_in[31]};
    float* out = (float*)d_out;

    const int TB = 256;
    // CSR build (shared across all 4 layers)
    k_zero_cnt<<<(NBINS + TB - 1) / TB, TB>>>();
    k_hist<<<(ETR + TB - 1) / TB, TB>>>(tei, tet);
    k_scan<<<1, 1024>>>();
    k_scatter<<<(ETR + TB - 1) / TB, TB>>>(tei, tet);

    // input transform -> bufA (stride 16)
    k_transform<<<(NN * 16 + TB - 1) / TB, TB>>>(xp, xm, Wp, bp, Wm, bm);

    // layer dims: (16,32) (32,32) (32,32) (32,16); buffers ping-pong A->B->A->B->A
    const int ins[4]  = {16, 32, 32, 32};
    const int outs[4] = {32, 32, 32, 16};
    int inA = 1;
    for (int l = 0; l < 4; l++) {
        int sz = ins[l] * outs[l];
        k_precompW<<<(2 * sz + TB - 1) / TB, TB>>>(bases[l], comp[l], ins[l], outs[l]);
        k_aggregate<<<(NBINS * 32 + TB - 1) / TB, TB>>>(inA, ins[l]);
        k_combine<<<(NN * outs[l] + TB - 1) / TB, TB>>>(inA, ins[l], outs[l],
                                                        root[l], bias[l], l < 3 ? 1 : 0);
        inA ^= 1;
    }
    // after 4 layers output is in bufA (inA==1 again), stride 16

    k_decode<<<(EDC * 16 + TB - 1) / TB, TB>>>(pei, pet, Wd0, bd0, Wd1, bd1, out);
    k_decode<<<(EDC * 16 + TB - 1) / TB, TB>>>(nei, net_, Wd0, bd0, Wd1, bd1, out + EDC);
}

// round 3
// speedup vs baseline: 1.0646x; 1.0646x over previous
#include <cuda_runtime.h>

#define NP 60000
#define NM 30000
#define NN 90000
#define ETR 2000000
#define EDC 400000
#define NBINS (2*NN)

// ---------------- device scratch (16B-aligned via float4/int4) ---------------
__device__ float4 g_bufA4[NN * 8];          // up to 32 floats / node
__device__ float4 g_bufB4[NN * 8];
__device__ float4 g_agg4[NN * 2 * 8];       // [bin][ins]
__device__ int    g_cnt[NBINS];
__device__ int    g_off[NBINS];
__device__ int    g_cur[NBINS];
__device__ int    g_esrc[ETR];
__device__ float  g_Wall[4 * 2048];         // per layer: W0 @ +0, W1 @ +1024

// ---------------- CSR build --------------------------------------------------
__global__ void k_zero_cnt() {
    int i = blockIdx.x * blockDim.x + threadIdx.x;
    if (i < NBINS) g_cnt[i] = 0;
}

__global__ void k_hist(const int* __restrict__ ei, const int* __restrict__ et) {
    int t = blockIdx.x * blockDim.x + threadIdx.x;
    int e = t * 2;
    if (e >= ETR) return;
    int2 d = *(const int2*)&ei[ETR + e];
    int2 r = *(const int2*)&et[e];
    atomicAdd(&g_cnt[d.x * 2 + r.x], 1);
    atomicAdd(&g_cnt[d.y * 2 + r.y], 1);
}

// single-block exclusive scan over NBINS bins
__global__ void k_scan() {
    __shared__ int ssum[1024];
    const int t = threadIdx.x;
    const int chunk = (NBINS + 1023) / 1024;
    int b0 = t * chunk;
    int b1 = min(b0 + chunk, NBINS);
    int s = 0;
    for (int i = b0; i < b1; i++) s += g_cnt[i];
    ssum[t] = s;
    __syncthreads();
    for (int off = 1; off < 1024; off <<= 1) {
        int tmp = (t >= off) ? ssum[t - off] : 0;
        __syncthreads();
        ssum[t] += tmp;
        __syncthreads();
    }
    int run = ssum[t] - s;
    for (int i = b0; i < b1; i++) {
        g_off[i] = run;
        g_cur[i] = run;
        run += g_cnt[i];
    }
}

__global__ void k_scatter(const int* __restrict__ ei, const int* __restrict__ et) {
    int t = blockIdx.x * blockDim.x + threadIdx.x;
    int e = t * 2;
    if (e >= ETR) return;
    int2 sv = *(const int2*)&ei[e];
    int2 d  = *(const int2*)&ei[ETR + e];
    int2 r  = *(const int2*)&et[e];
    int p0 = atomicAdd(&g_cur[d.x * 2 + r.x], 1);
    g_esrc[p0] = sv.x;
    int p1 = atomicAdd(&g_cur[d.y * 2 + r.y], 1);
    g_esrc[p1] = sv.y;
}

// ---------------- input transform --------------------------------------------
__global__ void k_transform(const float* __restrict__ xp, const float* __restrict__ xm,
                            const float* __restrict__ Wp, const float* __restrict__ bp,
                            const float* __restrict__ Wm, const float* __restrict__ bm) {
    int idx = blockIdx.x * blockDim.x + threadIdx.x;
    int n = idx >> 4;
    int o = idx & 15;
    if (n >= NN) return;
    const float* x;
    const float* W;
    float bv;
    if (n < NP) { x = xp + (long)n * 128; W = Wp; bv = __ldg(&bp[o]); }
    else        { x = xm + (long)(n - NP) * 128; W = Wm; bv = __ldg(&bm[o]); }
    float s = bv;
#pragma unroll 8
    for (int k = 0; k < 128; k++) s += __ldg(&x[k]) * __ldg(&W[k * 16 + o]);
    ((float*)g_bufA4)[n * 16 + o] = s;
}

// ---------------- all-layer basis combine ------------------------------------
// layer slot sizes (floats per relation, padded to 1024): total 2*4*1024 = 8192
__global__ void k_precompAll(const float* __restrict__ b1, const float* __restrict__ c1,
                             const float* __restrict__ b2, const float* __restrict__ c2,
                             const float* __restrict__ b3, const float* __restrict__ c3,
                             const float* __restrict__ b4, const float* __restrict__ c4) {
    int tid = blockIdx.x * blockDim.x + threadIdx.x;
    // layer sizes: 512, 1024, 1024, 512 (per relation)
    const int sizes[4] = {512, 1024, 1024, 512};
    const float* bases[4] = {b1, b2, b3, b4};
    const float* comp[4]  = {c1, c2, c3, c4};
    // total work items = 2*(512+1024+1024+512) = 6144
    if (tid >= 6144) return;
    int rem = tid;
    int l = 0;
    while (rem >= 2 * sizes[l]) { rem -= 2 * sizes[l]; l++; }
    int sz = sizes[l];
    int r = rem / sz;
    int io = rem - r * sz;
    float s = 0.f;
#pragma unroll
    for (int b = 0; b < 4; b++) s += __ldg(&comp[l][r * 4 + b]) * __ldg(&bases[l][b * sz + io]);
    g_Wall[l * 2048 + r * 1024 + io] = s;
}

// ---------------- segmented gather-mean: thread per (bin, float4 chunk) ------
template <int CHS>  // ins = 4 << CHS ; chunks per row = 1<<CHS
__global__ void k_aggregate(int inA) {
    const int CH = 1 << CHS;
    int tid = blockIdx.x * blockDim.x + threadIdx.x;
    int w = tid >> CHS;
    if (w >= NBINS) return;
    int c = tid & (CH - 1);
    const float4* __restrict__ xin = inA ? g_bufA4 : g_bufB4;
    int base = __ldg(&g_off[w]);
    int cnt  = __ldg(&g_cnt[w]);
    const int* ep = g_esrc + base;
    float4 s0 = make_float4(0.f, 0.f, 0.f, 0.f), s1 = s0, s2 = s0, s3 = s0;
    int i = 0;
    for (; i + 4 <= cnt; i += 4) {
        int a = __ldg(ep + i), b = __ldg(ep + i + 1);
        int d = __ldg(ep + i + 2), e = __ldg(ep + i + 3);
        float4 va = __ldg(xin + (a << CHS) + c);
        float4 vb = __ldg(xin + (b << CHS) + c);
        float4 vd = __ldg(xin + (d << CHS) + c);
        float4 ve = __ldg(xin + (e << CHS) + c);
        s0.x += va.x; s0.y += va.y; s0.z += va.z; s0.w += va.w;
        s1.x += vb.x; s1.y += vb.y; s1.z += vb.z; s1.w += vb.w;
        s2.x += vd.x; s2.y += vd.y; s2.z += vd.z; s2.w += vd.w;
        s3.x += ve.x; s3.y += ve.y; s3.z += ve.z; s3.w += ve.w;
    }
    for (; i < cnt; i++) {
        int a = __ldg(ep + i);
        float4 va = __ldg(xin + (a << CHS) + c);
        s0.x += va.x; s0.y += va.y; s0.z += va.z; s0.w += va.w;
    }
    float inv = cnt > 0 ? 1.0f / (float)cnt : 0.0f;
    float4 r;
    r.x = ((s0.x + s1.x) + (s2.x + s3.x)) * inv;
    r.y = ((s0.y + s1.y) + (s2.y + s3.y)) * inv;
    r.z = ((s0.z + s1.z) + (s2.z + s3.z)) * inv;
    r.w = ((s0.w + s1.w) + (s2.w + s3.w)) * inv;
    g_agg4[(w << CHS) + c] = r;
}

// ---------------- dense combine ----------------------------------------------
template <int INS, int OUTS>
__global__ void k_combine(int inA, int layer,
                          const float* __restrict__ root, const float* __restrict__ bias,
                          int do_relu) {
    int idx = blockIdx.x * blockDim.x + threadIdx.x;
    int n = idx / OUTS;
    int o = idx - n * OUTS;
    if (n >= NN) return;
    const float* __restrict__ xin  = inA ? (const float*)g_bufA4 : (const float*)g_bufB4;
    float* __restrict__ xout       = inA ? (float*)g_bufB4 : (float*)g_bufA4;
    const float* xr = xin + n * INS;
    const float* a0 = (const float*)g_agg4 + (n * 2) * INS;
    const float* a1 = a0 + INS;
    const float* W0 = g_Wall + layer * 2048;
    const float* W1 = W0 + 1024;
    float s = __ldg(&bias[o]);
#pragma unroll
    for (int i = 0; i < INS; i++) {
        s += xr[i] * __ldg(&root[i * OUTS + o]);
        s += a0[i] * W0[i * OUTS + o];
        s += a1[i] * W1[i * OUTS + o];
    }
    if (do_relu) s = fmaxf(s, 0.f);
    xout[n * OUTS + o] = s;
}

// ---------------- decoder: half-warp per edge, pos+neg fused -----------------
__global__ void k_decode(const int* __restrict__ pei, const int* __restrict__ pet,
                         const int* __restrict__ nei, const int* __restrict__ net,
                         const float* __restrict__ Wd0, const float* __restrict__ bd0,
                         const float* __restrict__ Wd1, const float* __restrict__ bd1,
                         float* __restrict__ out) {
    __shared__ float sW0[256], sW1[256], sb0[16], sb1[16];
    int tid = threadIdx.x;
    if (tid < 256) { sW0[tid] = Wd0[tid]; sW1[tid] = Wd1[tid]; }
    if (tid < 16) { sb0[tid] = bd0[tid]; sb1[tid] = bd1[tid]; }
    __syncthreads();
    int g = blockIdx.x * blockDim.x + tid;
    int e = g >> 4;
    int c = g & 15;
    if (e >= 2 * EDC) return;
    const int* ei;
    const int* et;
    int le;
    float* o;
    if (e < EDC) { ei = pei; et = pet; le = e; o = out; }
    else         { ei = nei; et = net; le = e - EDC; o = out + EDC; }
    const float* z = (const float*)g_bufA4;  // final embeddings, stride 16
    int src = __ldg(&ei[le]);
    int dst = __ldg(&ei[EDC + le]);
    int t = __ldg(&et[le]);
    float zs = __ldg(&z[src * 16 + c]);
    float zd = __ldg(&z[dst * 16 + c]);
    const float* W = (t == 0) ? sW0 : sW1;
    float h = (t == 0) ? sb0[c] : sb1[c];
#pragma unroll
    for (int i = 0; i < 16; i++) {
        float zi = __shfl_sync(0xffffffffu, zs, i, 16);
        h += zi * W[i * 16 + c];
    }
    float p = h * zd;
#pragma unroll
    for (int off = 8; off >= 1; off >>= 1)
        p += __shfl_down_sync(0xffffffffu, p, off, 16);
    if (c == 0) o[le] = p;
}

// ---------------- launch -----------------------------------------------------
extern "C" void kernel_launch(void* const* d_in, const int* in_sizes, int n_in,
                              void* d_out, int out_size) {
    const float* xp   = (const float*)d_in[0];
    const float* xm   = (const float*)d_in[1];
    const int*   tei  = (const int*)d_in[2];
    const int*   tet  = (const int*)d_in[3];
    const int*   pei  = (const int*)d_in[4];
    const int*   pet  = (const int*)d_in[5];
    const int*   nei  = (const int*)d_in[6];
    const int*   net_ = (const int*)d_in[7];
    const float* Wp   = (const float*)d_in[8];
    const float* bp   = (const float*)d_in[9];
    const float* Wm   = (const float*)d_in[10];
    const float* bm   = (const float*)d_in[11];
    const float* Wd0  = (const float*)d_in[12];
    const float* bd0  = (const float*)d_in[13];
    const float* Wd1  = (const float*)d_in[14];
    const float* bd1  = (const float*)d_in[15];
    const float* bases[4] = {(const float*)d_in[16], (const float*)d_in[20],
                             (const float*)d_in[24], (const float*)d_in[28]};
    const float* comp[4]  = {(const float*)d_in[17], (const float*)d_in[21],
                             (const float*)d_in[25], (const float*)d_in[29]};
    const float* root[4]  = {(const float*)d_in[18], (const float*)d_in[22],
                             (const float*)d_in[26], (const float*)d_in[30]};
    const float* bias[4]  = {(const float*)d_in[19], (const float*)d_in[23],
                             (const float*)d_in[27], (const float*)d_in[31]};
    float* out = (float*)d_out;

    const int TB = 256;
    // CSR build (shared across all 4 layers)
    k_zero_cnt<<<(NBINS + TB - 1) / TB, TB>>>();
    k_hist<<<(ETR / 2 + TB - 1) / TB, TB>>>(tei, tet);
    k_scan<<<1, 1024>>>();
    k_scatter<<<(ETR / 2 + TB - 1) / TB, TB>>>(tei, tet);

    // input transform -> bufA (stride 16) ; basis combine for all layers
    k_transform<<<(NN * 16 + TB - 1) / TB, TB>>>(xp, xm, Wp, bp, Wm, bm);
    k_precompAll<<<(6144 + TB - 1) / TB, TB>>>(bases[0], comp[0], bases[1], comp[1],
                                               bases[2], comp[2], bases[3], comp[3]);

    // layers: (16,32) (32,32) (32,32) (32,16); ping-pong A->B->A->B->A
    // layer 0: in stride 16 (CHS=2)
    k_aggregate<2><<<(NBINS * 4 + TB - 1) / TB, TB>>>(1);
    k_combine<16, 32><<<(NN * 32 + TB - 1) / TB, TB>>>(1, 0, root[0], bias[0], 1);
    // layer 1: in stride 32 (CHS=3)
    k_aggregate<3><<<(NBINS * 8 + TB - 1) / TB, TB>>>(0);
    k_combine<32, 32><<<(NN * 32 + TB - 1) / TB, TB>>>(0, 1, root[1], bias[1], 1);
    // layer 2
    k_aggregate<3><<<(NBINS * 8 + TB - 1) / TB, TB>>>(1);
    k_combine<32, 32><<<(NN * 32 + TB - 1) / TB, TB>>>(1, 2, root[2], bias[2], 1);
    // layer 3: out 16, no relu
    k_aggregate<3><<<(NBINS * 8 + TB - 1) / TB, TB>>>(0);
    k_combine<32, 16><<<(NN * 16 + TB - 1) / TB, TB>>>(0, 3, root[3], bias[3], 0);

    // decode (pos + neg fused); final z in bufA, stride 16
    k_decode<<<(2 * EDC * 16 + TB - 1) / TB, TB>>>(pei, pet, nei, net_,
                                                   Wd0, bd0, Wd1, bd1, out);
}

// round 5
// speedup vs baseline: 2.1599x; 2.0289x over previous
#include <cuda_runtime.h>

#define NP 60000
#define NM 30000
#define NN 90000
#define ETR 2000000
#define EDC 400000
#define NBINS (2*NN)
#define NBLK ((NBINS + 1023) / 1024)   // 176 scan blocks

// ---------------- device scratch ---------------------------------------------
__device__ float4 g_bufA4[NN * 8];
__device__ float4 g_bufB4[NN * 8];
__device__ float4 g_agg4[NN * 2 * 8];
__device__ int    g_cnt[NBINS];
__device__ int    g_off[NBINS];
__device__ int    g_cur[NBINS];
__device__ int    g_esrc[ETR];
__device__ float  g_Wall[4 * 2048];
__device__ int    g_blk[NBLK];
__device__ int    g_blkoff[NBLK];

// ---------------- CSR build --------------------------------------------------
__global__ void k_zero_cnt() {
    int i = blockIdx.x * blockDim.x + threadIdx.x;
    if (i < NBINS) g_cnt[i] = 0;
}

__global__ void k_hist(const int* __restrict__ ei, const int* __restrict__ et) {
    int t = blockIdx.x * blockDim.x + threadIdx.x;
    int e = t * 2;
    if (e >= ETR) return;
    int2 d = *(const int2*)&ei[ETR + e];
    int2 r = *(const int2*)&et[e];
    atomicAdd(&g_cnt[d.x * 2 + r.x], 1);
    atomicAdd(&g_cnt[d.y * 2 + r.y], 1);
}

// pass A: per-block sums (each block covers 1024 bins, int4-coalesced)
__global__ void k_scan_partial() {
    __shared__ int sh[256];
    int b = blockIdx.x, t = threadIdx.x;
    int base = b * 1024 + t * 4;
    int s = 0;
    if (base < NBINS) {
        int4 v = *(const int4*)&g_cnt[base];
        s = v.x + v.y + v.z + v.w;
    }
    sh[t] = s;
    __syncthreads();
    for (int off = 128; off >= 1; off >>= 1) {
        if (t < off) sh[t] += sh[t + off];
        __syncthreads();
    }
    if (t == 0) g_blk[b] = sh[0];
}

// pass B: exclusive scan of the 176 block totals (1 tiny block)
__global__ void k_scan_block() {
    __shared__ int sh[256];
    int t = threadIdx.x;
    int v = (t < NBLK) ? g_blk[t] : 0;
    sh[t] = v;
    __syncthreads();
    for (int off = 1; off < 256; off <<= 1) {
        int tmp = (t >= off) ? sh[t - off] : 0;
        __syncthreads();
        sh[t] += tmp;
        __syncthreads();
    }
    if (t < NBLK) g_blkoff[t] = sh[t] - v;
}

// pass C: per-block exclusive scan + global offset, write off/cur
__global__ void k_scan_final() {
    __shared__ int sh[256];
    int b = blockIdx.x, t = threadIdx.x;
    int base = b * 1024 + t * 4;
    int4 v = make_int4(0, 0, 0, 0);
    if (base < NBINS) v = *(const int4*)&g_cnt[base];
    int s = v.x + v.y + v.z + v.w;
    sh[t] = s;
    __syncthreads();
    for (int off = 1; off < 256; off <<= 1) {
        int tmp = (t >= off) ? sh[t - off] : 0;
        __syncthreads();
        sh[t] += tmp;
        __syncthreads();
    }
    if (base < NBINS) {
        int run = sh[t] - s + g_blkoff[b];
        int4 o;
        o.x = run;           run += v.x;
        o.y = run;           run += v.y;
        o.z = run;           run += v.z;
        o.w = run;
        *(int4*)&g_off[base] = o;
        *(int4*)&g_cur[base] = o;
    }
}

__global__ void k_scatter(const int* __restrict__ ei, const int* __restrict__ et) {
    int t = blockIdx.x * blockDim.x + threadIdx.x;
    int e = t * 2;
    if (e >= ETR) return;
    int2 sv = *(const int2*)&ei[e];
    int2 d  = *(const int2*)&ei[ETR + e];
    int2 r  = *(const int2*)&et[e];
    int p0 = atomicAdd(&g_cur[d.x * 2 + r.x], 1);
    g_esrc[p0] = sv.x;
    int p1 = atomicAdd(&g_cur[d.y * 2 + r.y], 1);
    g_esrc[p1] = sv.y;
}

// ---------------- input transform --------------------------------------------
__global__ void k_transform(const float* __restrict__ xp, const float* __restrict__ xm,
                            const float* __restrict__ Wp, const float* __restrict__ bp,
                            const float* __restrict__ Wm, const float* __restrict__ bm) {
    int idx = blockIdx.x * blockDim.x + threadIdx.x;
    int n = idx >> 4;
    int o = idx & 15;
    if (n >= NN) return;
    const float* x;
    const float* W;
    float bv;
    if (n < NP) { x = xp + (long)n * 128; W = Wp; bv = __ldg(&bp[o]); }
    else        { x = xm + (long)(n - NP) * 128; W = Wm; bv = __ldg(&bm[o]); }
    float s = bv;
#pragma unroll 8
    for (int k = 0; k < 128; k++) s += __ldg(&x[k]) * __ldg(&W[k * 16 + o]);
    ((float*)g_bufA4)[n * 16 + o] = s;
}

// ---------------- all-layer basis combine ------------------------------------
__global__ void k_precompAll(const float* __restrict__ b1, const float* __restrict__ c1,
                             const float* __restrict__ b2, const float* __restrict__ c2,
                             const float* __restrict__ b3, const float* __restrict__ c3,
                             const float* __restrict__ b4, const float* __restrict__ c4) {
    int tid = blockIdx.x * blockDim.x + threadIdx.x;
    const int sizes[4] = {512, 1024, 1024, 512};
    const float* bases[4] = {b1, b2, b3, b4};
    const float* comp[4]  = {c1, c2, c3, c4};
    if (tid >= 6144) return;
    int rem = tid;
    int l = 0;
    while (rem >= 2 * sizes[l]) { rem -= 2 * sizes[l]; l++; }
    int sz = sizes[l];
    int r = rem / sz;
    int io = rem - r * sz;
    float s = 0.f;
#pragma unroll
    for (int b = 0; b < 4; b++) s += __ldg(&comp[l][r * 4 + b]) * __ldg(&bases[l][b * sz + io]);
    g_Wall[l * 2048 + r * 1024 + io] = s;
}

// ---------------- segmented gather-mean: thread per (bin, float4 chunk) ------
template <int CHS>
__global__ void k_aggregate(int inA) {
    const int CH = 1 << CHS;
    int tid = blockIdx.x * blockDim.x + threadIdx.x;
    int w = tid >> CHS;
    if (w >= NBINS) return;
    int c = tid & (CH - 1);
    const float4* __restrict__ xin = inA ? g_bufA4 : g_bufB4;
    int base = __ldg(&g_off[w]);
    int cnt  = __ldg(&g_cnt[w]);
    const int* ep = g_esrc + base;
    float4 s0 = make_float4(0.f, 0.f, 0.f, 0.f), s1 = s0, s2 = s0, s3 = s0;
    int i = 0;
    for (; i + 4 <= cnt; i += 4) {
        int a = __ldg(ep + i), b = __ldg(ep + i + 1);
        int d = __ldg(ep + i + 2), e = __ldg(ep + i + 3);
        float4 va = __ldg(xin + (a << CHS) + c);
        float4 vb = __ldg(xin + (b << CHS) + c);
        float4 vd = __ldg(xin + (d << CHS) + c);
        float4 ve = __ldg(xin + (e << CHS) + c);
        s0.x += va.x; s0.y += va.y; s0.z += va.z; s0.w += va.w;
        s1.x += vb.x; s1.y += vb.y; s1.z += vb.z; s1.w += vb.w;
        s2.x += vd.x; s2.y += vd.y; s2.z += vd.z; s2.w += vd.w;
        s3.x += ve.x; s3.y += ve.y; s3.z += ve.z; s3.w += ve.w;
    }
    for (; i < cnt; i++) {
        int a = __ldg(ep + i);
        float4 va = __ldg(xin + (a << CHS) + c);
        s0.x += va.x; s0.y += va.y; s0.z += va.z; s0.w += va.w;
    }
    float inv = cnt > 0 ? 1.0f / (float)cnt : 0.0f;
    float4 r;
    r.x = ((s0.x + s1.x) + (s2.x + s3.x)) * inv;
    r.y = ((s0.y + s1.y) + (s2.y + s3.y)) * inv;
    r.z = ((s0.z + s1.z) + (s2.z + s3.z)) * inv;
    r.w = ((s0.w + s1.w) + (s2.w + s3.w)) * inv;
    g_agg4[(w << CHS) + c] = r;
}

// ---------------- dense combine: 2 nodes/thread, smem weights ----------------
template <int INS, int OUTS>
__global__ __launch_bounds__(128)
void k_combine(int inA, int layer,
               const float* __restrict__ root, const float* __restrict__ bias,
               int do_relu) {
    __shared__ float sR[INS * OUTS], sW0[INS * OUTS], sW1[INS * OUTS], sb[OUTS];
    const float* W0g = g_Wall + layer * 2048;
    const float* W1g = W0g + 1024;
    for (int i = threadIdx.x; i < INS * OUTS; i += 128) {
        sR[i]  = __ldg(&root[i]);
        sW0[i] = W0g[i];
        sW1[i] = W1g[i];
    }
    if (threadIdx.x < OUTS) sb[threadIdx.x] = __ldg(&bias[threadIdx.x]);
    __syncthreads();

    int p = blockIdx.x * blockDim.x + threadIdx.x;   // node pair
    int n0 = p * 2;
    if (n0 >= NN) return;
    const int IV = INS / 4;
    const float4* __restrict__ xin = inA ? g_bufA4 : g_bufB4;
    float* __restrict__ xout = inA ? (float*)g_bufB4 : (float*)g_bufA4;

    float acc0[OUTS], acc1[OUTS];
#pragma unroll
    for (int o = 0; o < OUTS; o++) { acc0[o] = sb[o]; acc1[o] = sb[o]; }

#pragma unroll
    for (int i4 = 0; i4 < IV; i4++) {
        float4 x0  = xin[n0 * IV + i4];
        float4 x1  = xin[(n0 + 1) * IV + i4];
        float4 p00 = g_agg4[(2 * n0) * IV + i4];
        float4 p01 = g_agg4[(2 * n0 + 1) * IV + i4];
        float4 p10 = g_agg4[(2 * n0 + 2) * IV + i4];
        float4 p11 = g_agg4[(2 * n0 + 3) * IV + i4];
        const float* xa0 = &x0.x;  const float* xa1 = &x1.x;
        const float* a00 = &p00.x; const float* a01 = &p01.x;
        const float* a10 = &p10.x; const float* a11 = &p11.x;
#pragma unroll
        for (int j = 0; j < 4; j++) {
            int i = i4 * 4 + j;
            float xv0 = xa0[j], av0 = a00[j], bv0 = a01[j];
            float xv1 = xa1[j], av1 = a10[j], bv1 = a11[j];
#pragma unroll
            for (int o = 0; o < OUTS; o++) {
                float r = sR[i * OUTS + o];
                float w0 = sW0[i * OUTS + o];
                float w1 = sW1[i * OUTS + o];
                acc0[o] += xv0 * r + av0 * w0 + bv0 * w1;
                acc1[o] += xv1 * r + av1 * w0 + bv1 * w1;
            }
        }
    }
    if (do_relu) {
#pragma unroll
        for (int o = 0; o < OUTS; o++) {
            acc0[o] = fmaxf(acc0[o], 0.f);
            acc1[o] = fmaxf(acc1[o], 0.f);
        }
    }
#pragma unroll
    for (int o4 = 0; o4 < OUTS / 4; o4++) {
        float4 v0 = make_float4(acc0[o4 * 4], acc0[o4 * 4 + 1], acc0[o4 * 4 + 2], acc0[o4 * 4 + 3]);
        float4 v1 = make_float4(acc1[o4 * 4], acc1[o4 * 4 + 1], acc1[o4 * 4 + 2], acc1[o4 * 4 + 3]);
        ((float4*)xout)[n0 * (OUTS / 4) + o4] = v0;
        ((float4*)xout)[(n0 + 1) * (OUTS / 4) + o4] = v1;
    }
}

// ---------------- decoder ----------------------------------------------------
__global__ void k_decode(const int* __restrict__ pei, const int* __restrict__ pet,
                         const int* __restrict__ nei, const int* __restrict__ net,
                         const float* __restrict__ Wd0, const float* __restrict__ bd0,
                         const float* __restrict__ Wd1, const float* __restrict__ bd1,
                         float* __restrict__ out) {
    __shared__ float sW0[256], sW1[256], sb0[16], sb1[16];
    int tid = threadIdx.x;
    if (tid < 256) { sW0[tid] = Wd0[tid]; sW1[tid] = Wd1[tid]; }
    if (tid < 16) { sb0[tid] = bd0[tid]; sb1[tid] = bd1[tid]; }
    __syncthreads();
    int g = blockIdx.x * blockDim.x + tid;
    int e = g >> 4;
    int c = g & 15;
    if (e >= 2 * EDC) return;
    const int* ei;
    const int* et;
    int le;
    float* o;
    if (e < EDC) { ei = pei; et = pet; le = e; o = out; }
    else         { ei = nei; et = net; le = e - EDC; o = out + EDC; }
    const float* z = (const float*)g_bufA4;
    int src = __ldg(&ei[le]);
    int dst = __ldg(&ei[EDC + le]);
    int t = __ldg(&et[le]);
    float zs = __ldg(&z[src * 16 + c]);
    float zd = __ldg(&z[dst * 16 + c]);
    const float* W = (t == 0) ? sW0 : sW1;
    float h = (t == 0) ? sb0[c] : sb1[c];
#pragma unroll
    for (int i = 0; i < 16; i++) {
        float zi = __shfl_sync(0xffffffffu, zs, i, 16);
        h += zi * W[i * 16 + c];
    }
    float p = h * zd;
#pragma unroll
    for (int off = 8; off >= 1; off >>= 1)
        p += __shfl_down_sync(0xffffffffu, p, off, 16);
    if (c == 0) o[le] = p;
}

// ---------------- launch -----------------------------------------------------
extern "C" void kernel_launch(void* const* d_in, const int* in_sizes, int n_in,
                              void* d_out, int out_size) {
    const float* xp   = (const float*)d_in[0];
    const float* xm   = (const float*)d_in[1];
    const int*   tei  = (const int*)d_in[2];
    const int*   tet  = (const int*)d_in[3];
    const int*   pei  = (const int*)d_in[4];
    const int*   pet  = (const int*)d_in[5];
    const int*   nei  = (const int*)d_in[6];
    const int*   net_ = (const int*)d_in[7];
    const float* Wp   = (const float*)d_in[8];
    const float* bp   = (const float*)d_in[9];
    const float* Wm   = (const float*)d_in[10];
    const float* bm   = (const float*)d_in[11];
    const float* Wd0  = (const float*)d_in[12];
    const float* bd0  = (const float*)d_in[13];
    const float* Wd1  = (const float*)d_in[14];
    const float* bd1  = (const float*)d_in[15];
    const float* bases[4] = {(const float*)d_in[16], (const float*)d_in[20],
                             (const float*)d_in[24], (const float*)d_in[28]};
    const float* comp[4]  = {(const float*)d_in[17], (const float*)d_in[21],
                             (const float*)d_in[25], (const float*)d_in[29]};
    const float* root[4]  = {(const float*)d_in[18], (const float*)d_in[22],
                             (const float*)d_in[26], (const float*)d_in[30]};
    const float* bias[4]  = {(const float*)d_in[19], (const float*)d_in[23],
                             (const float*)d_in[27], (const float*)d_in[31]};
    float* out = (float*)d_out;

    const int TB = 256;
    // CSR build
    k_zero_cnt<<<(NBINS + TB - 1) / TB, TB>>>();
    k_hist<<<(ETR / 2 + TB - 1) / TB, TB>>>(tei, tet);
    k_scan_partial<<<NBLK, 256>>>();
    k_scan_block<<<1, 256>>>();
    k_scan_final<<<NBLK, 256>>>();
    k_scatter<<<(ETR / 2 + TB - 1) / TB, TB>>>(tei, tet);

    // input transform + basis combine
    k_transform<<<(NN * 16 + TB - 1) / TB, TB>>>(xp, xm, Wp, bp, Wm, bm);
    k_precompAll<<<(6144 + TB - 1) / TB, TB>>>(bases[0], comp[0], bases[1], comp[1],
                                               bases[2], comp[2], bases[3], comp[3]);

    // layers (16,32) (32,32) (32,32) (32,16); ping-pong A->B->A->B->A
    const int PAIRS = NN / 2;
    k_aggregate<2><<<(NBINS * 4 + TB - 1) / TB, TB>>>(1);
    k_combine<16, 32><<<(PAIRS + 127) / 128, 128>>>(1, 0, root[0], bias[0], 1);
    k_aggregate<3><<<(NBINS * 8 + TB - 1) / TB, TB>>>(0);
    k_combine<32, 32><<<(PAIRS + 127) / 128, 128>>>(0, 1, root[1], bias[1], 1);
    k_aggregate<3><<<(NBINS * 8 + TB - 1) / TB, TB>>>(1);
    k_combine<32, 32><<<(PAIRS + 127) / 128, 128>>>(1, 2, root[2], bias[2], 1);
    k_aggregate<3><<<(NBINS * 8 + TB - 1) / TB, TB>>>(0);
    k_combine<32, 16><<<(PAIRS + 127) / 128, 128>>>(0, 3, root[3], bias[3], 0);

    // decode (pos + neg fused); final z in bufA, stride 16
    k_decode<<<(2 * EDC * 16 + TB - 1) / TB, TB>>>(pei, pet, nei, net_,
                                                   Wd0, bd0, Wd1, bd1, out);
}

// round 6
// speedup vs baseline: 2.4848x; 1.1504x over previous
#include <cuda_runtime.h>

#define NP 60000
#define NM 30000
#define NN 90000
#define ETR 2000000
#define EDC 400000
#define NBINS (2*NN)
#define NBLK ((NBINS + 1023) / 1024)   // 176 scan blocks
#define TFBLK 176                       // transform blocks (128 thr * 4 nodes)
#define PCBLK 48                        // precomp blocks (6144 threads / 128)

// ---------------- device scratch ---------------------------------------------
__device__ float4 g_bufA4[NN * 8];
__device__ float4 g_bufB4[NN * 8];
__device__ float4 g_agg4[NN * 2 * 8];
__device__ int    g_cnt[NBINS];
__device__ int    g_off[NBINS];
__device__ int    g_cur[NBINS];
__device__ int    g_esrc[ETR];
__device__ float  g_Wall[4 * 2048];
__device__ int    g_blk[NBLK];

// ---------------- CSR build --------------------------------------------------
__global__ void k_zero_cnt() {
    int i = blockIdx.x * blockDim.x + threadIdx.x;
    if (i * 4 < NBINS) *(int4*)&g_cnt[i * 4] = make_int4(0, 0, 0, 0);
}

__global__ void k_hist(const int* __restrict__ ei, const int* __restrict__ et) {
    int t = blockIdx.x * blockDim.x + threadIdx.x;
    int e = t * 4;
    if (e >= ETR) return;
    int4 d = *(const int4*)&ei[ETR + e];
    int4 r = *(const int4*)&et[e];
    atomicAdd(&g_cnt[d.x * 2 + r.x], 1);
    atomicAdd(&g_cnt[d.y * 2 + r.y], 1);
    atomicAdd(&g_cnt[d.z * 2 + r.z], 1);
    atomicAdd(&g_cnt[d.w * 2 + r.w], 1);
}

// pass A: per-block sums (each block covers 1024 bins, int4-coalesced)
__global__ void k_scan_partial() {
    __shared__ int sh[256];
    int b = blockIdx.x, t = threadIdx.x;
    int base = b * 1024 + t * 4;
    int s = 0;
    if (base < NBINS) {
        int4 v = *(const int4*)&g_cnt[base];
        s = v.x + v.y + v.z + v.w;
    }
    sh[t] = s;
    __syncthreads();
    for (int off = 128; off >= 1; off >>= 1) {
        if (t < off) sh[t] += sh[t + off];
        __syncthreads();
    }
    if (t == 0) g_blk[b] = sh[0];
}

// pass B (fused): per-block prefix from g_blk + local exclusive scan, write off/cur
__global__ void k_scan_final() {
    __shared__ int rs[256];
    __shared__ int sh[256];
    int b = blockIdx.x, t = threadIdx.x;
    int pv = (t < b) ? g_blk[t] : 0;     // b <= 175 < NBLK, safe
    rs[t] = pv;
    __syncthreads();
    for (int off = 128; off >= 1; off >>= 1) {
        if (t < off) rs[t] += rs[t + off];
        __syncthreads();
    }
    int blkoff = rs[0];

    int base = b * 1024 + t * 4;
    int4 v = make_int4(0, 0, 0, 0);
    if (base < NBINS) v = *(const int4*)&g_cnt[base];
    int s = v.x + v.y + v.z + v.w;
    sh[t] = s;
    __syncthreads();
    for (int off = 1; off < 256; off <<= 1) {
        int tmp = (t >= off) ? sh[t - off] : 0;
        __syncthreads();
        sh[t] += tmp;
        __syncthreads();
    }
    if (base < NBINS) {
        int run = sh[t] - s + blkoff;
        int4 o;
        o.x = run;           run += v.x;
        o.y = run;           run += v.y;
        o.z = run;           run += v.z;
        o.w = run;
        *(int4*)&g_off[base] = o;
        *(int4*)&g_cur[base] = o;
    }
}

__global__ void k_scatter(const int* __restrict__ ei, const int* __restrict__ et) {
    int t = blockIdx.x * blockDim.x + threadIdx.x;
    int e = t * 4;
    if (e >= ETR) return;
    int4 sv = *(const int4*)&ei[e];
    int4 d  = *(const int4*)&ei[ETR + e];
    int4 r  = *(const int4*)&et[e];
    int p0 = atomicAdd(&g_cur[d.x * 2 + r.x], 1);
    int p1 = atomicAdd(&g_cur[d.y * 2 + r.y], 1);
    int p2 = atomicAdd(&g_cur[d.z * 2 + r.z], 1);
    int p3 = atomicAdd(&g_cur[d.w * 2 + r.w], 1);
    g_esrc[p0] = sv.x;
    g_esrc[p1] = sv.y;
    g_esrc[p2] = sv.z;
    g_esrc[p3] = sv.w;
}

// ---------------- input transform (4 nodes/thread) + fused basis combine -----
__global__ __launch_bounds__(128)
void k_transform_precomp(const float* __restrict__ xp, const float* __restrict__ xm,
                         const float* __restrict__ Wp, const float* __restrict__ bp,
                         const float* __restrict__ Wm, const float* __restrict__ bm,
                         const float* __restrict__ b1, const float* __restrict__ c1,
                         const float* __restrict__ b2, const float* __restrict__ c2,
                         const float* __restrict__ b3, const float* __restrict__ c3,
                         const float* __restrict__ b4, const float* __restrict__ c4) {
    if (blockIdx.x >= TFBLK) {
        // ---- precomp path: combine bases -> g_Wall ----
        int tid = (blockIdx.x - TFBLK) * 128 + threadIdx.x;
        const int sizes[4] = {512, 1024, 1024, 512};
        const float* bases[4] = {b1, b2, b3, b4};
        const float* comp[4]  = {c1, c2, c3, c4};
        if (tid >= 6144) return;
        int rem = tid;
        int l = 0;
        while (rem >= 2 * sizes[l]) { rem -= 2 * sizes[l]; l++; }
        int sz = sizes[l];
        int r = rem / sz;
        int io = rem - r * sz;
        float s = 0.f;
#pragma unroll
        for (int b = 0; b < 4; b++)
            s += __ldg(&comp[l][r * 4 + b]) * __ldg(&bases[l][b * sz + io]);
        g_Wall[l * 2048 + r * 1024 + io] = s;
        return;
    }

    // ---- transform path ----
    __shared__ float4 sWp[512], sWm[512];     // [k][o4] : Wp[k][o4*4..+3]
    __shared__ float  sbp[16], sbm[16];
    int t = threadIdx.x;
    for (int i = t; i < 512; i += 128) {
        sWp[i] = __ldg((const float4*)Wp + i);
        sWm[i] = __ldg((const float4*)Wm + i);
    }
    if (t < 16) { sbp[t] = __ldg(&bp[t]); sbm[t] = __ldg(&bm[t]); }
    __syncthreads();

    int n0 = (blockIdx.x * 128 + t) * 4;
    if (n0 >= NN) return;
    bool paper = (n0 < NP);                   // 60000 % 4 == 0 -> uniform per thread
    const float4* xb = paper ? ((const float4*)xp + (long)n0 * 32)
                             : ((const float4*)xm + (long)(n0 - NP) * 32);
    const float4* W  = paper ? sWp : sWm;
    const float*  sb = paper ? sbp : sbm;

    float acc[4][16];
#pragma unroll
    for (int m = 0; m < 4; m++)
#pragma unroll
        for (int o = 0; o < 16; o++) acc[m][o] = sb[o];

    for (int k4 = 0; k4 < 32; k4++) {
        float4 xv[4];
#pragma unroll
        for (int m = 0; m < 4; m++) xv[m] = __ldg(xb + m * 32 + k4);
#pragma unroll
        for (int j = 0; j < 4; j++) {
            float xs0 = ((const float*)&xv[0])[j];
            float xs1 = ((const float*)&xv[1])[j];
            float xs2 = ((const float*)&xv[2])[j];
            float xs3 = ((const float*)&xv[3])[j];
            int k = k4 * 4 + j;
#pragma unroll
            for (int o4 = 0; o4 < 4; o4++) {
                float4 wv = W[k * 4 + o4];   // warp-uniform -> broadcast LDS
                acc[0][o4*4+0] += xs0 * wv.x; acc[0][o4*4+1] += xs0 * wv.y;
                acc[0][o4*4+2] += xs0 * wv.z; acc[0][o4*4+3] += xs0 * wv.w;
                acc[1][o4*4+0] += xs1 * wv.x; acc[1][o4*4+1] += xs1 * wv.y;
                acc[1][o4*4+2] += xs1 * wv.z; acc[1][o4*4+3] += xs1 * wv.w;
                acc[2][o4*4+0] += xs2 * wv.x; acc[2][o4*4+1] += xs2 * wv.y;
                acc[2][o4*4+2] += xs2 * wv.z; acc[2][o4*4+3] += xs2 * wv.w;
                acc[3][o4*4+0] += xs3 * wv.x; acc[3][o4*4+1] += xs3 * wv.y;
                acc[3][o4*4+2] += xs3 * wv.z; acc[3][o4*4+3] += xs3 * wv.w;
            }
        }
    }
#pragma unroll
    for (int m = 0; m < 4; m++)
#pragma unroll
        for (int o4 = 0; o4 < 4; o4++)
            g_bufA4[(n0 + m) * 4 + o4] = make_float4(acc[m][o4*4+0], acc[m][o4*4+1],
                                                     acc[m][o4*4+2], acc[m][o4*4+3]);
}

// ---------------- segmented gather-mean: thread per (bin, float4 chunk) ------
template <int CHS>
__global__ void k_aggregate(int inA) {
    const int CH = 1 << CHS;
    int tid = blockIdx.x * blockDim.x + threadIdx.x;
    int w = tid >> CHS;
    if (w >= NBINS) return;
    int c = tid & (CH - 1);
    const float4* __restrict__ xin = inA ? g_bufA4 : g_bufB4;
    int base = __ldg(&g_off[w]);
    int cnt  = __ldg(&g_cnt[w]);
    const int* ep = g_esrc + base;
    float4 s0 = make_float4(0.f, 0.f, 0.f, 0.f), s1 = s0, s2 = s0, s3 = s0;
    int i = 0;
    for (; i + 4 <= cnt; i += 4) {
        int a = __ldg(ep + i), b = __ldg(ep + i + 1);
        int d = __ldg(ep + i + 2), e = __ldg(ep + i + 3);
        float4 va = __ldg(xin + (a << CHS) + c);
        float4 vb = __ldg(xin + (b << CHS) + c);
        float4 vd = __ldg(xin + (d << CHS) + c);
        float4 ve = __ldg(xin + (e << CHS) + c);
        s0.x += va.x; s0.y += va.y; s0.z += va.z; s0.w += va.w;
        s1.x += vb.x; s1.y += vb.y; s1.z += vb.z; s1.w += vb.w;
        s2.x += vd.x; s2.y += vd.y; s2.z += vd.z; s2.w += vd.w;
        s3.x += ve.x; s3.y += ve.y; s3.z += ve.z; s3.w += ve.w;
    }
    for (; i < cnt; i++) {
        int a = __ldg(ep + i);
        float4 va = __ldg(xin + (a << CHS) + c);
        s0.x += va.x; s0.y += va.y; s0.z += va.z; s0.w += va.w;
    }
    float inv = cnt > 0 ? 1.0f / (float)cnt : 0.0f;
    float4 r;
    r.x = ((s0.x + s1.x) + (s2.x + s3.x)) * inv;
    r.y = ((s0.y + s1.y) + (s2.y + s3.y)) * inv;
    r.z = ((s0.z + s1.z) + (s2.z + s3.z)) * inv;
    r.w = ((s0.w + s1.w) + (s2.w + s3.w)) * inv;
    g_agg4[(w << CHS) + c] = r;
}

// ---------------- dense combine: 2 nodes/thread, smem weights ----------------
template <int INS, int OUTS>
__global__ __launch_bounds__(128)
void k_combine(int inA, int layer,
               const float* __restrict__ root, const float* __restrict__ bias,
               int do_relu) {
    __shared__ float sR[INS * OUTS], sW0[INS * OUTS], sW1[INS * OUTS], sb[OUTS];
    const float* W0g = g_Wall + layer * 2048;
    const float* W1g = W0g + 1024;
    for (int i = threadIdx.x; i < INS * OUTS; i += 128) {
        sR[i]  = __ldg(&root[i]);
        sW0[i] = W0g[i];
        sW1[i] = W1g[i];
    }
    if (threadIdx.x < OUTS) sb[threadIdx.x] = __ldg(&bias[threadIdx.x]);
    __syncthreads();

    int p = blockIdx.x * blockDim.x + threadIdx.x;
    int n0 = p * 2;
    if (n0 >= NN) return;
    const int IV = INS / 4;
    const float4* __restrict__ xin = inA ? g_bufA4 : g_bufB4;
    float* __restrict__ xout = inA ? (float*)g_bufB4 : (float*)g_bufA4;

    float acc0[OUTS], acc1[OUTS];
#pragma unroll
    for (int o = 0; o < OUTS; o++) { acc0[o] = sb[o]; acc1[o] = sb[o]; }

#pragma unroll 2
    for (int i4 = 0; i4 < IV; i4++) {
        float4 x0  = xin[n0 * IV + i4];
        float4 x1  = xin[(n0 + 1) * IV + i4];
        float4 p00 = g_agg4[(2 * n0) * IV + i4];
        float4 p01 = g_agg4[(2 * n0 + 1) * IV + i4];
        float4 p10 = g_agg4[(2 * n0 + 2) * IV + i4];
        float4 p11 = g_agg4[(2 * n0 + 3) * IV + i4];
        const float* xa0 = &x0.x;  const float* xa1 = &x1.x;
        const float* a00 = &p00.x; const float* a01 = &p01.x;
        const float* a10 = &p10.x; const float* a11 = &p11.x;
#pragma unroll
        for (int j = 0; j < 4; j++) {
            int i = i4 * 4 + j;
            float xv0 = xa0[j], av0 = a00[j], bv0 = a01[j];
            float xv1 = xa1[j], av1 = a10[j], bv1 = a11[j];
#pragma unroll
            for (int o = 0; o < OUTS; o++) {
                float r = sR[i * OUTS + o];
                float w0 = sW0[i * OUTS + o];
                float w1 = sW1[i * OUTS + o];
                acc0[o] += xv0 * r + av0 * w0 + bv0 * w1;
                acc1[o] += xv1 * r + av1 * w0 + bv1 * w1;
            }
        }
    }
    if (do_relu) {
#pragma unroll
        for (int o = 0; o < OUTS; o++) {
            acc0[o] = fmaxf(acc0[o], 0.f);
            acc1[o] = fmaxf(acc1[o], 0.f);
        }
    }
#pragma unroll
    for (int o4 = 0; o4 < OUTS / 4; o4++) {
        float4 v0 = make_float4(acc0[o4 * 4], acc0[o4 * 4 + 1], acc0[o4 * 4 + 2], acc0[o4 * 4 + 3]);
        float4 v1 = make_float4(acc1[o4 * 4], acc1[o4 * 4 + 1], acc1[o4 * 4 + 2], acc1[o4 * 4 + 3]);
        ((float4*)xout)[n0 * (OUTS / 4) + o4] = v0;
        ((float4*)xout)[(n0 + 1) * (OUTS / 4) + o4] = v1;
    }
}

// ---------------- decoder ----------------------------------------------------
__global__ void k_decode(const int* __restrict__ pei, const int* __restrict__ pet,
                         const int* __restrict__ nei, const int* __restrict__ net,
                         const float* __restrict__ Wd0, const float* __restrict__ bd0,
                         const float* __restrict__ Wd1, const float* __restrict__ bd1,
                         float* __restrict__ out) {
    __shared__ float sW0[256], sW1[256], sb0[16], sb1[16];
    int tid = threadIdx.x;
    if (tid < 256) { sW0[tid] = Wd0[tid]; sW1[tid] = Wd1[tid]; }
    if (tid < 16) { sb0[tid] = bd0[tid]; sb1[tid] = bd1[tid]; }
    __syncthreads();
    int g = blockIdx.x * blockDim.x + tid;
    int e = g >> 4;
    int c = g & 15;
    if (e >= 2 * EDC) return;
    const int* ei;
    const int* et;
    int le;
    float* o;
    if (e < EDC) { ei = pei; et = pet; le = e; o = out; }
    else         { ei = nei; et = net; le = e - EDC; o = out + EDC; }
    const float* z = (const float*)g_bufA4;
    int src = __ldg(&ei[le]);
    int dst = __ldg(&ei[EDC + le]);
    int t = __ldg(&et[le]);
    float zs = __ldg(&z[src * 16 + c]);
    float zd = __ldg(&z[dst * 16 + c]);
    const float* W = (t == 0) ? sW0 : sW1;
    float h = (t == 0) ? sb0[c] : sb1[c];
#pragma unroll
    for (int i = 0; i < 16; i++) {
        float zi = __shfl_sync(0xffffffffu, zs, i, 16);
        h += zi * W[i * 16 + c];
    }
    float p = h * zd;
#pragma unroll
    for (int off = 8; off >= 1; off >>= 1)
        p += __shfl_down_sync(0xffffffffu, p, off, 16);
    if (c == 0) o[le] = p;
}

// ---------------- launch -----------------------------------------------------
extern "C" void kernel_launch(void* const* d_in, const int* in_sizes, int n_in,
                              void* d_out, int out_size) {
    const float* xp   = (const float*)d_in[0];
    const float* xm   = (const float*)d_in[1];
    const int*   tei  = (const int*)d_in[2];
    const int*   tet  = (const int*)d_in[3];
    const int*   pei  = (const int*)d_in[4];
    const int*   pet  = (const int*)d_in[5];
    const int*   nei  = (const int*)d_in[6];
    const int*   net_ = (const int*)d_in[7];
    const float* Wp   = (const float*)d_in[8];
    const float* bp   = (const float*)d_in[9];
    const float* Wm   = (const float*)d_in[10];
    const float* bm   = (const float*)d_in[11];
    const float* Wd0  = (const float*)d_in[12];
    const float* bd0  = (const float*)d_in[13];
    const float* Wd1  = (const float*)d_in[14];
    const float* bd1  = (const float*)d_in[15];
    const float* bases[4] = {(const float*)d_in[16], (const float*)d_in[20],
                             (const float*)d_in[24], (const float*)d_in[28]};
    const float* comp[4]  = {(const float*)d_in[17], (const float*)d_in[21],
                             (const float*)d_in[25], (const float*)d_in[29]};
    const float* root[4]  = {(const float*)d_in[18], (const float*)d_in[22],
                             (const float*)d_in[26], (const float*)d_in[30]};
    const float* bias[4]  = {(const float*)d_in[19], (const float*)d_in[23],
                             (const float*)d_in[27], (const float*)d_in[31]};
    float* out = (float*)d_out;

    const int TB = 256;
    // 1: zero, 2: hist, 3: partial, 4: transform+precomp (profiled slot), 5: final, 6: scatter
    k_zero_cnt<<<(NBINS / 4 + TB - 1) / TB, TB>>>();
    k_hist<<<(ETR / 4 + TB - 1) / TB, TB>>>(tei, tet);
    k_scan_partial<<<NBLK, 256>>>();
    k_transform_precomp<<<TFBLK + PCBLK, 128>>>(xp, xm, Wp, bp, Wm, bm,
                                                bases[0], comp[0], bases[1], comp[1],
                                                bases[2], comp[2], bases[3], comp[3]);
    k_scan_final<<<NBLK, 256>>>();
    k_scatter<<<(ETR / 4 + TB - 1) / TB, TB>>>(tei, tet);

    // layers (16,32) (32,32) (32,32) (32,16); ping-pong A->B->A->B->A
    const int PAIRS = NN / 2;
    k_aggregate<2><<<(NBINS * 4 + TB - 1) / TB, TB>>>(1);
    k_combine<16, 32><<<(PAIRS + 127) / 128, 128>>>(1, 0, root[0], bias[0], 1);
    k_aggregate<3><<<(NBINS * 8 + TB - 1) / TB, TB>>>(0);
    k_combine<32, 32><<<(PAIRS + 127) / 128, 128>>>(0, 1, root[1], bias[1], 1);
    k_aggregate<3><<<(NBINS * 8 + TB - 1) / TB, TB>>>(1);
    k_combine<32, 32><<<(PAIRS + 127) / 128, 128>>>(1, 2, root[2], bias[2], 1);
    k_aggregate<3><<<(NBINS * 8 + TB - 1) / TB, TB>>>(0);
    k_combine<32, 16><<<(PAIRS + 127) / 128, 128>>>(0, 3, root[3], bias[3], 0);

    // decode (pos + neg fused); final z in bufA, stride 16
    k_decode<<<(2 * EDC * 16 + TB - 1) / TB, TB>>>(pei, pet, nei, net_,
                                                   Wd0, bd0, Wd1, bd1, out);
}